// round 3
// baseline (speedup 1.0000x reference)
#include <cuda_runtime.h>
#include <math.h>

// Problem constants (fixed shapes from reference)
#define BB 4
#define SS 12
#define NN 4096
#define CC 64
#define HH 128
#define BS (BB*SS)              // 48
#define XEMB_PER_BS (NN*HH)     // 524288
#define OUT_ELEMS (BS*NN*HH)    // 25165824
#define A_ELEMS (NN*NN)         // 16777216

// Scratch (device globals, no runtime allocation)
__device__ float g_d[NN];
__device__ float g_xemb[OUT_ELEMS];   // [bs][n][h] fp32, ~100 MB

// ---------------------------------------------------------------------------
// Kernel 1: d[i] = rsqrt(rowsum(A[i,:]) + 1)
// ---------------------------------------------------------------------------
__global__ void rowsum_kernel(const float* __restrict__ A) {
    int row = blockIdx.x;
    const float4* Arow = (const float4*)(A + (size_t)row * NN);
    float s = 0.f;
    for (int idx = threadIdx.x; idx < NN / 4; idx += blockDim.x) {
        float4 v = Arow[idx];
        s += v.x + v.y + v.z + v.w;
    }
    __shared__ float red[8];
    #pragma unroll
    for (int o = 16; o > 0; o >>= 1) s += __shfl_down_sync(0xffffffffu, s, o);
    if ((threadIdx.x & 31) == 0) red[threadIdx.x >> 5] = s;
    __syncthreads();
    if (threadIdx.x < 8) {
        float t = red[threadIdx.x];
        #pragma unroll
        for (int o = 4; o > 0; o >>= 1) t += __shfl_down_sync(0xffu, t, o);
        if (threadIdx.x == 0) g_d[row] = rsqrtf(t + 1.0f);
    }
}

// ---------------------------------------------------------------------------
// Kernel 2: x_emb[row, h] = sum_c x[row, c] * W[h, c]   (row = bs*N + n)
// 128 threads/block (one thread per h), 8 rows per block.
// ---------------------------------------------------------------------------
#define EMB_ROWS 8
__global__ __launch_bounds__(128) void emb_kernel(const float* __restrict__ x,
                                                  const float* __restrict__ W) {
    __shared__ float Ws[HH * (CC + 1)];     // padded (stride 65) -> conflict-free
    __shared__ float xs[EMB_ROWS][CC];
    int t = threadIdx.x;
    for (int i = t; i < HH * CC; i += 128) {
        int h = i / CC, c = i % CC;
        Ws[h * (CC + 1) + c] = W[i];
    }
    size_t row0 = (size_t)blockIdx.x * EMB_ROWS;
    const float* xb = x + row0 * CC;
    for (int i = t; i < EMB_ROWS * CC; i += 128)
        xs[i / CC][i % CC] = xb[i];
    __syncthreads();

    const float* wrow = &Ws[t * (CC + 1)];
    #pragma unroll
    for (int r = 0; r < EMB_ROWS; r++) {
        float s = 0.f;
        #pragma unroll
        for (int c = 0; c < CC; c++) s += xs[r][c] * wrow[c];
        g_xemb[(row0 + r) * HH + t] = s;
    }
}

// ---------------------------------------------------------------------------
// Kernel 3: fused Y = A @ (d * x_emb),  out = sigmoid(x_emb - d ∘ Y)
// Tile 128x128, K-tile 8, 256 threads, 8x8 micro-tile per thread.
// Column tile == one (b,s) slice (128 cols/bs), so epilogue is trivially
// addressable. Z is formed on the fly at the B-tile load (multiply by d[k]).
// ---------------------------------------------------------------------------
#define TM 128
#define TN 128
#define TK 8
__global__ __launch_bounds__(256) void gemm_kernel(const float* __restrict__ A,
                                                   float* __restrict__ out) {
    __shared__ float As[TK][TM];
    __shared__ float Bs[TK][TN];
    int bs = blockIdx.x;                 // 0..47 -> column tile == (b,s) slice
    int i0 = blockIdx.y * TM;            // row tile
    int t  = threadIdx.x;
    int tx = t & 15, ty = t >> 4;        // 16x16 thread grid, 8x8 each

    const float* xe = g_xemb + (size_t)bs * XEMB_PER_BS;

    // A-load mapping: thread loads float4 of 4 consecutive k
    int ai = t >> 1;
    int ak = (t & 1) * 4;
    // B-load mapping: thread loads float4 of 4 consecutive h for one k
    int bk = t >> 5;
    int bj = (t & 31) * 4;

    float acc[8][8];
    #pragma unroll
    for (int u = 0; u < 8; u++)
        #pragma unroll
        for (int v = 0; v < 8; v++) acc[u][v] = 0.f;

    for (int k0 = 0; k0 < NN; k0 += TK) {
        float4 av = *(const float4*)&A[(size_t)(i0 + ai) * NN + k0 + ak];
        As[ak + 0][ai] = av.x;
        As[ak + 1][ai] = av.y;
        As[ak + 2][ai] = av.z;
        As[ak + 3][ai] = av.w;

        float dk = g_d[k0 + bk];
        float4 bv = *(const float4*)&xe[(size_t)(k0 + bk) * HH + bj];
        Bs[bk][bj + 0] = dk * bv.x;
        Bs[bk][bj + 1] = dk * bv.y;
        Bs[bk][bj + 2] = dk * bv.z;
        Bs[bk][bj + 3] = dk * bv.w;
        __syncthreads();

        #pragma unroll
        for (int kk = 0; kk < TK; kk++) {
            float4 a0 = *(const float4*)&As[kk][ty * 8];
            float4 a1 = *(const float4*)&As[kk][ty * 8 + 4];
            float4 b0 = *(const float4*)&Bs[kk][tx * 8];
            float4 b1 = *(const float4*)&Bs[kk][tx * 8 + 4];
            float a[8] = {a0.x, a0.y, a0.z, a0.w, a1.x, a1.y, a1.z, a1.w};
            float b[8] = {b0.x, b0.y, b0.z, b0.w, b1.x, b1.y, b1.z, b1.w};
            #pragma unroll
            for (int u = 0; u < 8; u++)
                #pragma unroll
                for (int v = 0; v < 8; v++)
                    acc[u][v] += a[u] * b[v];
        }
        __syncthreads();
    }

    // Epilogue: out = sigmoid(x_emb - d[i] * Y)
    #pragma unroll
    for (int u = 0; u < 8; u++) {
        int i = i0 + ty * 8 + u;
        float di = g_d[i];
        size_t base = (size_t)bs * XEMB_PER_BS + (size_t)i * HH;
        #pragma unroll
        for (int v = 0; v < 8; v++) {
            int j = tx * 8 + v;
            float hval = xe[(size_t)i * HH + j] - di * acc[u][v];
            out[base + j] = 1.0f / (1.0f + expf(-hval));
        }
    }
}

// ---------------------------------------------------------------------------
// Kernel 4: pass-through copy of A into the tail of d_out (tuple output)
// ---------------------------------------------------------------------------
__global__ void copyA_kernel(const float* __restrict__ A, float* __restrict__ dst) {
    size_t i = (size_t)blockIdx.x * blockDim.x + threadIdx.x;
    ((float4*)dst)[i] = ((const float4*)A)[i];
}

// ---------------------------------------------------------------------------
extern "C" void kernel_launch(void* const* d_in, const int* in_sizes, int n_in,
                              void* d_out, int out_size) {
    const float* x = (const float*)d_in[0];
    const float* A = (const float*)d_in[1];
    const float* W = (const float*)d_in[2];
    float* out = (float*)d_out;

    rowsum_kernel<<<NN, 256>>>(A);
    emb_kernel<<<(BS * NN) / EMB_ROWS, 128>>>(x, W);

    dim3 grid(BS, NN / TM);   // 48 x 32
    gemm_kernel<<<grid, 256>>>(A, out);

    if (out_size >= OUT_ELEMS + A_ELEMS) {
        // tuple output: (out, A) — copy A after the sigmoid block
        copyA_kernel<<<(A_ELEMS / 4) / 256, 256>>>(A, out + OUT_ELEMS);
    }
}

// round 7
// speedup vs baseline: 6.4918x; 6.4918x over previous
#include <cuda_runtime.h>
#include <cuda_bf16.h>
#include <cstdint>
#include <math.h>

// Problem constants (fixed shapes)
#define BB 4
#define SS 12
#define NN 4096
#define CC 64
#define HH 128
#define BS (BB*SS)              // 48
#define OUT_ELEMS (BS*NN*HH)    // 25165824
#define A_ELEMS (NN*NN)         // 16777216
#define JTOT (BS*HH)            // 6144

// Scratch (device globals; 16B aligned for vector/cp.async access)
__device__ __align__(16) float g_d[NN];
__device__ __align__(16) float g_xemb[OUT_ELEMS];              // fp32 [bs][n][h]
__device__ __align__(16) __nv_bfloat16 g_Abf[A_ELEMS];         // bf16 A
__device__ __align__(16) __nv_bfloat16 g_zT[(size_t)JTOT*NN];  // bf16 Z^T [j][k]

// ---------------------------------------------------------------------------
// PTX helpers (sm_103-legal: cp.async / ldmatrix / mma.sync only)
// ---------------------------------------------------------------------------
__device__ __forceinline__ void cpasync16(uint32_t saddr, const void* gaddr) {
    asm volatile("cp.async.cg.shared.global [%0], [%1], 16;" :: "r"(saddr), "l"(gaddr));
}
#define CP_COMMIT() asm volatile("cp.async.commit_group;" ::: "memory")
#define CP_WAIT(n)  asm volatile("cp.async.wait_group %0;" :: "n"(n) : "memory")

#define LDSM_X4(r0,r1,r2,r3,addr) \
    asm volatile("ldmatrix.sync.aligned.m8n8.x4.shared.b16 {%0,%1,%2,%3}, [%4];" \
        : "=r"(r0), "=r"(r1), "=r"(r2), "=r"(r3) : "r"(addr))

#define MMA16816(d, a0,a1,a2,a3, b0,b1) \
    asm volatile("mma.sync.aligned.m16n8k16.row.col.f32.bf16.bf16.f32 " \
        "{%0,%1,%2,%3}, {%4,%5,%6,%7}, {%8,%9}, {%0,%1,%2,%3};" \
        : "+f"((d)[0]), "+f"((d)[1]), "+f"((d)[2]), "+f"((d)[3]) \
        : "r"(a0), "r"(a1), "r"(a2), "r"(a3), "r"(b0), "r"(b1))

// ---------------------------------------------------------------------------
// Kernel 1: d[i] = rsqrt(rowsum(A[i,:]) + 1)
// ---------------------------------------------------------------------------
__global__ void rowsum_kernel(const float* __restrict__ A) {
    int row = blockIdx.x;
    const float4* Arow = (const float4*)(A + (size_t)row * NN);
    float s = 0.f;
    for (int idx = threadIdx.x; idx < NN / 4; idx += blockDim.x) {
        float4 v = Arow[idx];
        s += v.x + v.y + v.z + v.w;
    }
    __shared__ float red[8];
    #pragma unroll
    for (int o = 16; o > 0; o >>= 1) s += __shfl_down_sync(0xffffffffu, s, o);
    if ((threadIdx.x & 31) == 0) red[threadIdx.x >> 5] = s;
    __syncthreads();
    if (threadIdx.x < 8) {
        float t = red[threadIdx.x];
        #pragma unroll
        for (int o = 4; o > 0; o >>= 1) t += __shfl_down_sync(0xffu, t, o);
        if (threadIdx.x == 0) g_d[row] = rsqrtf(t + 1.0f);
    }
}

// ---------------------------------------------------------------------------
// Kernel 2: A (fp32) -> g_Abf (bf16)
// ---------------------------------------------------------------------------
__global__ void convA_kernel(const float* __restrict__ A) {
    size_t i = (size_t)blockIdx.x * blockDim.x + threadIdx.x;
    float4 v = ((const float4*)A)[i];
    alignas(8) __nv_bfloat16 b[4] = {
        __float2bfloat16(v.x), __float2bfloat16(v.y),
        __float2bfloat16(v.z), __float2bfloat16(v.w) };
    ((uint2*)g_Abf)[i] = *(const uint2*)b;
}

// ---------------------------------------------------------------------------
// Kernel 3: x_emb fp32 AND Z^T bf16 (Z^T[j][k] = d[k]*x_emb[bs,k,h], j=bs*128+h)
// ---------------------------------------------------------------------------
#define EMB_ROWS 8
__global__ __launch_bounds__(128) void emb_kernel(const float* __restrict__ x,
                                                  const float* __restrict__ W) {
    __shared__ float Ws[HH * (CC + 1)];
    __shared__ float xs[EMB_ROWS][CC];
    int t = threadIdx.x;
    for (int i = t; i < HH * CC; i += 128) Ws[(i / CC) * (CC + 1) + (i % CC)] = W[i];
    size_t row0 = (size_t)blockIdx.x * EMB_ROWS;
    const float* xb = x + row0 * CC;
    for (int i = t; i < EMB_ROWS * CC; i += 128) xs[i / CC][i % CC] = xb[i];
    __syncthreads();

    const float* wr = &Ws[t * (CC + 1)];
    float vals[EMB_ROWS];
    #pragma unroll
    for (int r = 0; r < EMB_ROWS; r++) {
        float s = 0.f;
        #pragma unroll
        for (int c = 0; c < CC; c++) s += xs[r][c] * wr[c];
        vals[r] = s;
        g_xemb[(row0 + r) * HH + t] = s;
    }
    int bs  = (int)(row0 >> 12);       // row0 / 4096
    int rib = (int)(row0 & 4095);      // k index within slice
    alignas(16) __nv_bfloat16 zb[8];
    #pragma unroll
    for (int r = 0; r < EMB_ROWS; r++)
        zb[r] = __float2bfloat16(g_d[rib + r] * vals[r]);
    *(uint4*)&g_zT[((size_t)(bs * HH + t)) * NN + rib] = *(const uint4*)zb;
}

// ---------------------------------------------------------------------------
// Kernel 4: HMMA GEMM  D = A_bf @ Z^T_bf  (CTA 128x128, warp 32x64),
//           fused epilogue out = sigmoid(x_emb - d[i]*D)
// ---------------------------------------------------------------------------
#define KCH 64
#define NCHUNK (NN / KCH)        // 64
#define PITCH 144                 // bytes per row (64 bf16 = 128B data + 16B skew)
#define TILE_BYTES (128 * PITCH)  // 18432
#define STAGE_BYTES (2 * TILE_BYTES)
#define SM_D_OFF (2 * STAGE_BYTES)          // 73728
#define SMEM_TOT (SM_D_OFF + 128 * 4)       // 74240

__global__ void __launch_bounds__(256, 2) gemm_mma(float* __restrict__ out) {
    extern __shared__ char smem[];
    const uint32_t sb = (uint32_t)__cvta_generic_to_shared(smem);
    const int tid = threadIdx.x;
    const int wid = tid >> 5, lid = tid & 31;
    const int warp_m = wid & 3, warp_n = wid >> 2;   // 4 x 2 warp grid
    const int bs = blockIdx.x;                        // N-tile == one (b,s) slice
    const int i0 = blockIdx.y * 128;                  // row tile base

    float* sD = (float*)(smem + SM_D_OFF);
    if (tid < 128) sD[tid] = g_d[i0 + tid];

    const __nv_bfloat16* Ag = g_Abf + (size_t)i0 * NN;
    const __nv_bfloat16* Bg = g_zT + (size_t)bs * HH * NN;

    // cp.async chunk mapping: 1024 chunks/operand/stage; 4 per thread each.
    // chunk c: row = c>>3, 16B-chunk kb = c&7
    auto load_stage = [&](int stage, int k0) {
        uint32_t aBase = sb + stage * STAGE_BYTES;
        uint32_t bBase = aBase + TILE_BYTES;
        #pragma unroll
        for (int u = 0; u < 4; u++) {
            int c = tid + u * 256;
            int row = c >> 3, kb = c & 7;
            cpasync16(aBase + row * PITCH + kb * 16, Ag + (size_t)row * NN + k0 + kb * 8);
            cpasync16(bBase + row * PITCH + kb * 16, Bg + (size_t)row * NN + k0 + kb * 8);
        }
        CP_COMMIT();
    };

    float acc[2][8][4];
    #pragma unroll
    for (int mb = 0; mb < 2; mb++)
        #pragma unroll
        for (int nb = 0; nb < 8; nb++)
            #pragma unroll
            for (int q = 0; q < 4; q++) acc[mb][nb][q] = 0.f;

    // ldmatrix per-lane address parts
    const int o = lid >> 3, r = lid & 7;
    // A: m = warp_m*32 + mb*16 + (o&1)*8 + r ; k = kk*16 + (o>>1)*8
    const int amPart = warp_m * 32 + (o & 1) * 8 + r;
    const int akPart = (o >> 1) * 8;
    // B: n = warp_n*64 + nb*16 + (o>=2)*8 + r ; k = kk*16 + (o&1)*8
    const int bnPart = warp_n * 64 + (o >> 1) * 8 + r;
    const int bkPart = (o & 1) * 8;

    load_stage(0, 0);

    for (int i = 0; i < NCHUNK; i++) {
        if (i + 1 < NCHUNK) load_stage((i + 1) & 1, (i + 1) * KCH);
        if (i + 1 < NCHUNK) { CP_WAIT(1); } else { CP_WAIT(0); }
        __syncthreads();

        const uint32_t aT = sb + (i & 1) * STAGE_BYTES;
        const uint32_t bT = aT + TILE_BYTES;

        #pragma unroll
        for (int kk = 0; kk < 4; kk++) {
            uint32_t a[2][4];
            #pragma unroll
            for (int mb = 0; mb < 2; mb++) {
                uint32_t addr = aT + (amPart + mb * 16) * PITCH + (kk * 16 + akPart) * 2;
                LDSM_X4(a[mb][0], a[mb][1], a[mb][2], a[mb][3], addr);
            }
            uint32_t b[4][4];
            #pragma unroll
            for (int nb = 0; nb < 4; nb++) {
                uint32_t addr = bT + (bnPart + nb * 16) * PITCH + (kk * 16 + bkPart) * 2;
                LDSM_X4(b[nb][0], b[nb][1], b[nb][2], b[nb][3], addr);
            }
            #pragma unroll
            for (int mb = 0; mb < 2; mb++)
                #pragma unroll
                for (int n8 = 0; n8 < 8; n8++) {
                    const uint32_t* bp = &b[n8 >> 1][(n8 & 1) * 2];
                    MMA16816(acc[mb][n8], a[mb][0], a[mb][1], a[mb][2], a[mb][3],
                             bp[0], bp[1]);
                }
        }
        __syncthreads();
    }

    // --- fused epilogue: out = sigmoid(x_emb - d[i]*acc) ---
    const float* xeB = g_xemb + (size_t)bs * NN * HH;
    float* outB = out + (size_t)bs * NN * HH;
    const int rq = lid >> 2, cq = (lid & 3) * 2;
    #pragma unroll
    for (int mb = 0; mb < 2; mb++) {
        #pragma unroll
        for (int half = 0; half < 2; half++) {     // c{0,1} vs c{2,3} (row, row+8)
            int rloc = warp_m * 32 + mb * 16 + rq + half * 8;
            int iG = i0 + rloc;
            float di = sD[rloc];
            const float* xe = xeB + (size_t)iG * HH;
            float* op = outB + (size_t)iG * HH;
            #pragma unroll
            for (int n8 = 0; n8 < 8; n8++) {
                int h = warp_n * 64 + n8 * 8 + cq;
                float2 xv = *(const float2*)(xe + h);
                float v0 = xv.x - di * acc[mb][n8][half * 2 + 0];
                float v1 = xv.y - di * acc[mb][n8][half * 2 + 1];
                float2 ov;
                ov.x = 1.0f / (1.0f + expf(-v0));
                ov.y = 1.0f / (1.0f + expf(-v1));
                *(float2*)(op + h) = ov;
            }
        }
    }
}

// ---------------------------------------------------------------------------
// Kernel 5: pass-through copy of A into tail of d_out
// ---------------------------------------------------------------------------
__global__ void copyA_kernel(const float* __restrict__ A, float* __restrict__ dst) {
    size_t i = (size_t)blockIdx.x * blockDim.x + threadIdx.x;
    ((float4*)dst)[i] = ((const float4*)A)[i];
}

// ---------------------------------------------------------------------------
extern "C" void kernel_launch(void* const* d_in, const int* in_sizes, int n_in,
                              void* d_out, int out_size) {
    const float* x = (const float*)d_in[0];
    const float* A = (const float*)d_in[1];
    const float* W = (const float*)d_in[2];
    float* out = (float*)d_out;

    cudaFuncSetAttribute(gemm_mma, cudaFuncAttributeMaxDynamicSharedMemorySize, SMEM_TOT);

    rowsum_kernel<<<NN, 256>>>(A);
    convA_kernel<<<(A_ELEMS / 4) / 256, 256>>>(A);
    emb_kernel<<<(BS * NN) / EMB_ROWS, 128>>>(x, W);

    dim3 grid(BS, NN / 128);   // 48 x 32
    gemm_mma<<<grid, 256, SMEM_TOT>>>(out);

    if (out_size >= OUT_ELEMS + A_ELEMS) {
        copyA_kernel<<<(A_ELEMS / 4) / 256, 256>>>(A, out + OUT_ELEMS);
    }
}